// round 6
// baseline (speedup 1.0000x reference)
#include <cuda_runtime.h>
#include <math.h>
#include <stdint.h>

// ---------------------------------------------------------------------------
// Problem constants
// ---------------------------------------------------------------------------
#define S_LEN   512
#define BATCH   64
#define D_IN    256
#define HID     512
#define G4      2048        // 4 gates * HID, packed unit-major: col = u*4 + gate
#define NH      4
#define DK      128
#define ROWS    (S_LEN*BATCH)        // 32768
#define DEC_ELEMS (S_LEN*BATCH*HID)  // 16777216
#define NB      128                  // persistent LSTM blocks
#define HPAD    516                  // padded h row (conflict-free, 16B-aligned rows)
#define WS_FLOATS (HID*16)           // 8192 floats weight slice
#define GP      72                   // gemm smem pitch (floats)

// ---------------------------------------------------------------------------
// Device scratch (static allocations only — no cudaMalloc allowed)
// ---------------------------------------------------------------------------
__device__ float g_Wxp[D_IN*G4];          //   2 MB  packed input-gate weights
__device__ float g_Whp[HID*G4];           //   4 MB  packed recurrent-gate weights
__device__ float g_biasp[G4];
__device__ float g_gx[ROWS*G4];           // 256 MB  x-side gate preacts; reused as attn scores
__device__ float g_lstm[ROWS*HID];        //  64 MB  lstm_out [S,B,HID]; doubles as h history
__device__ float g_c[BATCH*HID];
__device__ float g_PQ[ROWS*HID];          //  64 MB
__device__ float g_PK[ROWS*HID];
__device__ float g_PV[ROWS*HID];
__device__ unsigned g_cnt;                //  grid barrier counter

// ---------------------------------------------------------------------------
// Helpers
// ---------------------------------------------------------------------------
#define FMA2(d, a, b, c) \
    asm("fma.rn.f32x2 %0, %1, %2, %3;" : "=l"(d) : "l"(a), "l"(b), "l"(c))

__device__ __forceinline__ float sigmoid_fast(float x) {
    return 1.0f / (1.0f + __expf(-x));
}
__device__ __forceinline__ float tanh_fast2(float x) {
    return 1.0f - 2.0f / (__expf(2.0f * x) + 1.0f);
}
__device__ __forceinline__ float tf32_rnd(float x) {
    uint32_t u; asm("cvt.rna.tf32.f32 %0, %1;" : "=r"(u) : "f"(x));
    return __uint_as_float(u);
}
__device__ __forceinline__ uint32_t fu(float x) { return __float_as_uint(x); }

#define MMA8(cc, a, bb) \
    asm volatile("mma.sync.aligned.m16n8k8.row.col.f32.tf32.tf32.f32 " \
        "{%0,%1,%2,%3},{%4,%5,%6,%7},{%8,%9},{%0,%1,%2,%3};" \
        : "+f"(cc[0]), "+f"(cc[1]), "+f"(cc[2]), "+f"(cc[3]) \
        : "r"(a[0]), "r"(a[1]), "r"(a[2]), "r"(a[3]), "r"(bb[0]), "r"(bb[1]))

// ---------------------------------------------------------------------------
// Weight repack.
// ---------------------------------------------------------------------------
__global__ void pack_weights(const float* __restrict__ Wf, const float* __restrict__ Wi,
                             const float* __restrict__ Wg, const float* __restrict__ Wo,
                             const float* __restrict__ bf, const float* __restrict__ bi,
                             const float* __restrict__ bg, const float* __restrict__ bo)
{
    int idx = blockIdx.x * blockDim.x + threadIdx.x;   // over 768*512
    if (idx < 768*HID) {
        int k = idx / HID, u = idx % HID;
        float vf = Wf[idx], vi = Wi[idx], vg = Wg[idx], vo = Wo[idx];
        float* dst = (k < D_IN) ? (g_Wxp + (long)k*G4) : (g_Whp + (long)(k - D_IN)*G4);
        dst[u*4+0] = vf; dst[u*4+1] = vi; dst[u*4+2] = vg; dst[u*4+3] = vo;
    }
    if (idx < HID) {
        g_biasp[idx*4+0] = bf[idx];
        g_biasp[idx*4+1] = bi[idx];
        g_biasp[idx*4+2] = bg[idx];
        g_biasp[idx*4+3] = bo[idx];
    }
    if (idx == 0) g_cnt = 0u;
}

// ---------------------------------------------------------------------------
// tf32 3-split GEMM: C = alpha * A @ B(^T) + bias.
// A[M,K] row-major. transB=0: B[K,N] row-major; transB=1: B[N,K] row-major.
// Block: 64x64 tile, 128 threads (4 warps, 2x2 warp grid of 32x32).
// mma.sync m16n8k8 tf32, 3 passes (hi*hi, hi*lo, lo*hi)  => ~fp32 accuracy.
// A-fragment order (PTX ISA, tf32 m16n8k8): a0=(r,q) a1=(r+8,q) a2=(r,q+4)
// a3=(r+8,q+4);  B: b0=(q,r) b1=(q+4,r);  C: c0/c1=(r, 2q/2q+1) c2/c3=(r+8,..).
// Batched via blockIdx.z: offsets (z>>2)*s1 + (z&3)*s2.
// ---------------------------------------------------------------------------
__global__ __launch_bounds__(128)
void gemm_tf32(const float* __restrict__ A, int lda, long as1, long as2,
               const float* __restrict__ B, int ldb, long bs1, long bs2,
               const float* __restrict__ bias,
               float* __restrict__ C, int ldc, long cs1, long cs2,
               int K, float alpha, int transB)
{
    __shared__ float Ah[16*GP], Al[16*GP], Bh[16*GP], Bl[16*GP];

    int z = blockIdx.z;
    A += (long)(z >> 2) * as1 + (long)(z & 3) * as2;
    B += (long)(z >> 2) * bs1 + (long)(z & 3) * bs2;
    C += (long)(z >> 2) * cs1 + (long)(z & 3) * cs2;
    int m0 = blockIdx.y * 64, n0 = blockIdx.x * 64;

    int tid = threadIdx.x;
    int warp = tid >> 5, lane = tid & 31;
    int wm = (warp >> 1) * 32, wn = (warp & 1) * 32;
    int r = lane >> 2, q = lane & 3;

    float acc[2][4][4];
    #pragma unroll
    for (int mt = 0; mt < 2; mt++)
        #pragma unroll
        for (int nt = 0; nt < 4; nt++)
            #pragma unroll
            for (int e = 0; e < 4; e++) acc[mt][nt][e] = 0.f;

    for (int k0 = 0; k0 < K; k0 += 16) {
        // ---- stage A 64x16 -> As[k][m] (split hi/lo) ----
        #pragma unroll
        for (int i = 0; i < 2; i++) {
            int lin = tid + i*128;              // 0..255
            int ar = lin >> 2, aq = lin & 3;    // row 0..63, k-quad
            float4 v = *(const float4*)(A + (long)(m0 + ar)*lda + k0 + aq*4);
            float f[4] = {v.x, v.y, v.z, v.w};
            #pragma unroll
            for (int e = 0; e < 4; e++) {
                float hi = tf32_rnd(f[e]);
                Ah[(aq*4+e)*GP + ar] = hi;
                Al[(aq*4+e)*GP + ar] = tf32_rnd(f[e] - hi);
            }
        }
        // ---- stage B 16x64 -> Bs[k][n] ----
        if (!transB) {
            #pragma unroll
            for (int i = 0; i < 2; i++) {
                int lin = tid + i*128;
                int br = lin >> 4, bq = lin & 15;   // k row 0..15, n-quad
                float4 v = *(const float4*)(B + (long)(k0 + br)*ldb + n0 + bq*4);
                float f[4] = {v.x, v.y, v.z, v.w};
                #pragma unroll
                for (int e = 0; e < 4; e++) {
                    float hi = tf32_rnd(f[e]);
                    Bh[br*GP + bq*4 + e] = hi;
                    Bl[br*GP + bq*4 + e] = tf32_rnd(f[e] - hi);
                }
            }
        } else {
            #pragma unroll
            for (int i = 0; i < 2; i++) {
                int lin = tid + i*128;
                int bn = lin >> 2, bq = lin & 3;    // n row 0..63, k-quad
                float4 v = *(const float4*)(B + (long)(n0 + bn)*ldb + k0 + bq*4);
                float f[4] = {v.x, v.y, v.z, v.w};
                #pragma unroll
                for (int e = 0; e < 4; e++) {
                    float hi = tf32_rnd(f[e]);
                    Bh[(bq*4+e)*GP + bn] = hi;
                    Bl[(bq*4+e)*GP + bn] = tf32_rnd(f[e] - hi);
                }
            }
        }
        __syncthreads();

        #pragma unroll
        for (int p = 0; p < 2; p++) {
            int kb = p*8;
            uint32_t ah[2][4], al[2][4], bh[4][2], bl[4][2];
            #pragma unroll
            for (int mt = 0; mt < 2; mt++) {
                int m = wm + mt*16 + r;
                // tf32 m16n8k8 A order: (r,q), (r+8,q), (r,q+4), (r+8,q+4)
                ah[mt][0] = fu(Ah[(kb+q  )*GP + m    ]);
                ah[mt][1] = fu(Ah[(kb+q  )*GP + m + 8]);
                ah[mt][2] = fu(Ah[(kb+q+4)*GP + m    ]);
                ah[mt][3] = fu(Ah[(kb+q+4)*GP + m + 8]);
                al[mt][0] = fu(Al[(kb+q  )*GP + m    ]);
                al[mt][1] = fu(Al[(kb+q  )*GP + m + 8]);
                al[mt][2] = fu(Al[(kb+q+4)*GP + m    ]);
                al[mt][3] = fu(Al[(kb+q+4)*GP + m + 8]);
            }
            #pragma unroll
            for (int nt = 0; nt < 4; nt++) {
                int n = wn + nt*8 + r;
                bh[nt][0] = fu(Bh[(kb+q  )*GP + n]);
                bh[nt][1] = fu(Bh[(kb+q+4)*GP + n]);
                bl[nt][0] = fu(Bl[(kb+q  )*GP + n]);
                bl[nt][1] = fu(Bl[(kb+q+4)*GP + n]);
            }
            #pragma unroll
            for (int mt = 0; mt < 2; mt++)
                #pragma unroll
                for (int nt = 0; nt < 4; nt++) {
                    MMA8(acc[mt][nt], ah[mt], bh[nt]);
                    MMA8(acc[mt][nt], ah[mt], bl[nt]);
                    MMA8(acc[mt][nt], al[mt], bh[nt]);
                }
        }
        __syncthreads();
    }

    // ---- epilogue ----
    #pragma unroll
    for (int mt = 0; mt < 2; mt++)
        #pragma unroll
        for (int nt = 0; nt < 4; nt++) {
            int mrow = m0 + wm + mt*16 + r;
            int ncol = n0 + wn + nt*8 + q*2;
            float b0 = bias ? bias[ncol]   : 0.f;
            float b1 = bias ? bias[ncol+1] : 0.f;
            C[(long)mrow*ldc + ncol  ]     = alpha*acc[mt][nt][0] + b0;
            C[(long)mrow*ldc + ncol+1]     = alpha*acc[mt][nt][1] + b1;
            C[(long)(mrow+8)*ldc + ncol  ] = alpha*acc[mt][nt][2] + b0;
            C[(long)(mrow+8)*ldc + ncol+1] = alpha*acc[mt][nt][3] + b1;
        }
}

// ---------------------------------------------------------------------------
// Persistent LSTM recurrence. 128 blocks x 256 threads.
// Block bid owns hid-units [bid*4, bid*4+4) (packed cols [bid*16, bid*16+16)).
// Thread (b = tid>>2, cq = tid&3) produces all 4 gates of unit bid*4+cq,
// batch row b, with fma.rn.f32x2 over k-pairs.
// h history IS g_lstm: step t reads g_lstm[t-1] (t=0: zeros -> skip matvec).
// Grid barrier: tid0-only ld.acquire.gpu poll + red.release.gpu arrive.
// SMEM: pair-packed W slice wsp[kp*32 + j*2 + e] (32 KB) + staged h (129 KB).
// ---------------------------------------------------------------------------
__global__ __launch_bounds__(256)
void lstm_persistent(const float* __restrict__ gx)
{
    extern __shared__ float sm[];
    float* wsp = sm;                     // 8192 floats

    const int tid = threadIdx.x, bid = blockIdx.x;
    const int c0 = bid * 16;
    const int b  = tid >> 2, cq = tid & 3;
    const int u  = bid*4 + cq;

    // pair-packed weight slice: wsp[kp*32 + j*2 + e] = Whp[2kp+e][c0+j]
    for (int idx = tid; idx < WS_FLOATS; idx += 256) {
        int kp = idx >> 5, rr = idx & 31, j = rr >> 1, e = rr & 1;
        wsp[idx] = g_Whp[(long)(2*kp + e)*G4 + c0 + j];
    }

    const uint32_t smem0 = (uint32_t)__cvta_generic_to_shared(sm);
    const uint32_t hs0   = smem0 + WS_FLOATS*4;
    const uint32_t hrow  = hs0 + (uint32_t)(b*HPAD)*4;
    const uint32_t wbase = smem0 + (uint32_t)(cq*8)*4;

    float creg = 0.f;
    unsigned* cnt_p = &g_cnt;
    __syncthreads();

    for (int t = 0; t < S_LEN; t++) {
        // prefetch this thread's gx quad (immutable input)
        const float4 gv = __ldcs((const float4*)(gx + ((long)t*BATCH + b)*G4 + c0 + cq*4));

        float pf, pi, pg, po;
        if (t == 0) {
            pf = gv.x; pi = gv.y; pg = gv.z; po = gv.w;
        } else {
            // ---- grid barrier: all blocks done with step t-1 ----
            if (tid == 0) {
                unsigned target = (unsigned)t * NB, v;
                do {
                    asm volatile("ld.acquire.gpu.global.u32 %0, [%1];"
                                 : "=r"(v) : "l"(cnt_p) : "memory");
                } while (v < target);
            }
            __syncthreads();

            // ---- stage h_prev = g_lstm[t-1] via cp.async ----
            const float* hp = g_lstm + (long)(t-1)*BATCH*HID;
            #pragma unroll
            for (int i = 0; i < 32; i++) {
                int lin = tid + i*256;                // float4 idx 0..8191
                int rr = lin >> 7, cc = lin & 127;
                const float* src = hp + rr*HID + cc*4;
                uint32_t dst = hs0 + (uint32_t)(rr*HPAD + cc*4)*4;
                asm volatile("cp.async.cg.shared.global [%0], [%1], 16;"
                             :: "r"(dst), "l"(src));
            }
            asm volatile("cp.async.commit_group;");
            asm volatile("cp.async.wait_group 0;" ::: "memory");
            __syncthreads();

            // ---- matvec: 4 gate accumulators as f32x2 pairs ----
            unsigned long long a0 = 0ULL, a1 = 0ULL, a2 = 0ULL, a3 = 0ULL;
            #pragma unroll 8
            for (int k = 0; k < HID; k += 4) {
                unsigned long long h01, h23, w0, w1, w2, w3, w4, w5, w6, w7;
                asm("ld.shared.v2.u64 {%0,%1}, [%2];"
                    : "=l"(h01), "=l"(h23) : "r"(hrow + (uint32_t)k*4));
                uint32_t wk = wbase + (uint32_t)(k >> 1)*128;
                asm("ld.shared.v2.u64 {%0,%1}, [%2];"
                    : "=l"(w0), "=l"(w1) : "r"(wk));
                asm("ld.shared.v2.u64 {%0,%1}, [%2];"
                    : "=l"(w2), "=l"(w3) : "r"(wk + 16));
                asm("ld.shared.v2.u64 {%0,%1}, [%2];"
                    : "=l"(w4), "=l"(w5) : "r"(wk + 128));
                asm("ld.shared.v2.u64 {%0,%1}, [%2];"
                    : "=l"(w6), "=l"(w7) : "r"(wk + 144));
                FMA2(a0, h01, w0, a0);
                FMA2(a1, h01, w1, a1);
                FMA2(a2, h01, w2, a2);
                FMA2(a3, h01, w3, a3);
                FMA2(a0, h23, w4, a0);
                FMA2(a1, h23, w5, a1);
                FMA2(a2, h23, w6, a2);
                FMA2(a3, h23, w7, a3);
            }
            float e0, o0, e1, o1, e2, o2, e3, o3;
            asm("mov.b64 {%0,%1}, %2;" : "=f"(e0), "=f"(o0) : "l"(a0));
            asm("mov.b64 {%0,%1}, %2;" : "=f"(e1), "=f"(o1) : "l"(a1));
            asm("mov.b64 {%0,%1}, %2;" : "=f"(e2), "=f"(o2) : "l"(a2));
            asm("mov.b64 {%0,%1}, %2;" : "=f"(e3), "=f"(o3) : "l"(a3));
            pf = e0 + o0 + gv.x;
            pi = e1 + o1 + gv.y;
            pg = e2 + o2 + gv.z;
            po = e3 + o3 + gv.w;
        }

        float f  = sigmoid_fast(pf);
        float ii = sigmoid_fast(pi);
        float gg = tanh_fast2(pg);
        float o  = sigmoid_fast(po);
        creg = f * creg + ii * gg;
        float hn = o * tanh_fast2(creg);

        g_lstm[((long)t*BATCH + b)*HID + u] = hn;
        if (t == S_LEN-1) g_c[b*HID + u] = creg;

        // ---- arrive ----
        __syncthreads();
        if (tid == 0)
            asm volatile("red.release.gpu.global.add.u32 [%0], %1;"
                         :: "l"(cnt_p), "r"(1u) : "memory");
    }
}

// ---------------------------------------------------------------------------
// Row softmax over 512-wide rows. One block (128 threads) per row.
// ---------------------------------------------------------------------------
__global__ __launch_bounds__(128)
void softmax512(float* __restrict__ s)
{
    float* row = s + (size_t)blockIdx.x * 512;
    int tid = threadIdx.x;
    float v0 = row[tid], v1 = row[tid+128], v2 = row[tid+256], v3 = row[tid+384];
    float mx = fmaxf(fmaxf(v0, v1), fmaxf(v2, v3));
    __shared__ float sm[4];
    __shared__ float ss[4];
    #pragma unroll
    for (int off = 16; off > 0; off >>= 1)
        mx = fmaxf(mx, __shfl_xor_sync(0xFFFFFFFFu, mx, off));
    if ((tid & 31) == 0) sm[tid >> 5] = mx;
    __syncthreads();
    mx = fmaxf(fmaxf(sm[0], sm[1]), fmaxf(sm[2], sm[3]));
    v0 = expf(v0 - mx); v1 = expf(v1 - mx); v2 = expf(v2 - mx); v3 = expf(v3 - mx);
    float sum = v0 + v1 + v2 + v3;
    #pragma unroll
    for (int off = 16; off > 0; off >>= 1)
        sum += __shfl_xor_sync(0xFFFFFFFFu, sum, off);
    if ((tid & 31) == 0) ss[tid >> 5] = sum;
    __syncthreads();
    sum = ss[0] + ss[1] + ss[2] + ss[3];
    float inv = 1.f / sum;
    row[tid] = v0*inv; row[tid+128] = v1*inv; row[tid+256] = v2*inv; row[tid+384] = v3*inv;
}

__global__ void copy_hc(const float* __restrict__ hfin, const float* __restrict__ c,
                        float* __restrict__ out)
{
    int i = blockIdx.x * blockDim.x + threadIdx.x;
    if (i < BATCH*HID) {
        out[DEC_ELEMS + i] = hfin[i];
        out[DEC_ELEMS + BATCH*HID + i] = c[i];
    }
}

// ---------------------------------------------------------------------------
// Host orchestration (graph-capturable: launches only)
// ---------------------------------------------------------------------------
extern "C" void kernel_launch(void* const* d_in, const int* in_sizes, int n_in,
                              void* d_out, int out_size)
{
    const float* x  = (const float*)d_in[0];
    const float* Wf = (const float*)d_in[1];
    const float* bf = (const float*)d_in[2];
    const float* Wi = (const float*)d_in[3];
    const float* bi = (const float*)d_in[4];
    const float* Wg = (const float*)d_in[5];
    const float* bg = (const float*)d_in[6];
    const float* Wo = (const float*)d_in[7];
    const float* bo = (const float*)d_in[8];
    const float* Wq = (const float*)d_in[9];
    const float* bq = (const float*)d_in[10];
    const float* Wk = (const float*)d_in[11];
    const float* bk = (const float*)d_in[12];
    const float* Wv = (const float*)d_in[13];
    const float* bv = (const float*)d_in[14];
    float* out = (float*)d_out;

    float *Wxp, *biasp, *gx, *lstm, *c, *PQ, *PK, *PV;
    cudaGetSymbolAddress((void**)&Wxp,   g_Wxp);
    cudaGetSymbolAddress((void**)&biasp, g_biasp);
    cudaGetSymbolAddress((void**)&gx,    g_gx);
    cudaGetSymbolAddress((void**)&lstm,  g_lstm);
    cudaGetSymbolAddress((void**)&c,     g_c);
    cudaGetSymbolAddress((void**)&PQ,    g_PQ);
    cudaGetSymbolAddress((void**)&PK,    g_PK);
    cudaGetSymbolAddress((void**)&PV,    g_PV);

    const int SMEM_LSTM = (WS_FLOATS + BATCH*HPAD) * (int)sizeof(float);  // 164,864 B
    cudaFuncSetAttribute(lstm_persistent,
                         cudaFuncAttributeMaxDynamicSharedMemorySize, SMEM_LSTM);

    // 1. repack weights + reset barrier counter
    pack_weights<<<(768*HID + 255)/256, 256>>>(Wf, Wi, Wg, Wo, bf, bi, bg, bo);

    // 2. x-side gate preacts: gx = x @ Wxp + biasp   [32768,256]@[256,2048]
    gemm_tf32<<<dim3(G4/64, ROWS/64, 1), 128>>>(
        x, D_IN, 0, 0, Wxp, G4, 0, 0, biasp, gx, G4, 0, 0, D_IN, 1.0f, 0);

    // 3. recurrence: persistent kernel, device grid barrier per step
    lstm_persistent<<<NB, 256, SMEM_LSTM>>>(gx);

    // 4. Q/K/V projections: [32768,512]@[512,512]+b
    gemm_tf32<<<dim3(HID/64, ROWS/64, 1), 128>>>(
        lstm, HID, 0, 0, Wq, HID, 0, 0, bq, PQ, HID, 0, 0, HID, 1.0f, 0);
    gemm_tf32<<<dim3(HID/64, ROWS/64, 1), 128>>>(
        lstm, HID, 0, 0, Wk, HID, 0, 0, bk, PK, HID, 0, 0, HID, 1.0f, 0);
    gemm_tf32<<<dim3(HID/64, ROWS/64, 1), 128>>>(
        lstm, HID, 0, 0, Wv, HID, 0, 0, bv, PV, HID, 0, 0, HID, 1.0f, 0);

    // 5. scores = (Q @ K^T)/sqrt(dk), z = b'*4 + h
    const long pbS = (long)S_LEN * HID;          // per-b' stride in PQ/PK/PV
    const long phS = DK;                         // per-h stride
    const long scB = 4L * S_LEN * S_LEN;         // scores per-b' stride
    const long scH = (long)S_LEN * S_LEN;        // scores per-h stride
    float scale = 1.0f / sqrtf((float)DK);
    gemm_tf32<<<dim3(S_LEN/64, S_LEN/64, BATCH*NH), 128>>>(
        PQ, HID, pbS, phS,
        PK, HID, pbS, phS,
        (const float*)0,
        gx /* reused as scores */, S_LEN, scB, scH, DK, scale, 1);

    // 6. softmax over last axis
    softmax512<<<BATCH*NH*S_LEN, 128>>>(gx);

    // 7. out = attn @ V, written directly in decoded layout:
    //    d_out[(s*64 + b')*512 + h*128 + d]
    gemm_tf32<<<dim3(DK/64, S_LEN/64, BATCH*NH), 128>>>(
        gx, S_LEN, scB, scH,
        PV, HID, pbS, phS,
        (const float*)0,
        out, BATCH*HID, (long)HID, (long)DK, S_LEN, 1.0f, 0);

    // 8. final hidden/cell state (h_final = last lstm_out slice)
    copy_hc<<<(BATCH*HID + 255)/256, 256>>>(
        lstm + (long)(S_LEN-1)*BATCH*HID, c, out);
}

// round 7
// speedup vs baseline: 1.6042x; 1.6042x over previous
#include <cuda_runtime.h>
#include <math.h>
#include <stdint.h>

// ---------------------------------------------------------------------------
// Problem constants
// ---------------------------------------------------------------------------
#define S_LEN   512
#define BATCH   64
#define D_IN    256
#define HID     512
#define G4      2048        // 4 gates * HID, packed unit-major: col = u*4 + gate
#define NH      4
#define DK      128
#define ROWS    (S_LEN*BATCH)        // 32768
#define DEC_ELEMS (S_LEN*BATCH*HID)  // 16777216
#define NB      128                  // persistent LSTM blocks
#define HPAD    516                  // padded h row (bank-conflict-free)
#define APITCH  20                   // gemm A-smem pitch (floats, 80B = 16B-aligned)
#define BPITCH  72                   // gemm B-smem pitch, normal path (288B)

// ---------------------------------------------------------------------------
// Device scratch (static allocations only — no cudaMalloc allowed)
// ---------------------------------------------------------------------------
__device__ float g_Wxp[D_IN*G4];          //   2 MB  packed input-gate weights
__device__ float g_Whp[HID*G4];           //   4 MB  packed recurrent-gate weights
__device__ float g_biasp[G4];
__device__ float g_gx[ROWS*G4];           // 256 MB  x-side gate preacts; reused as attn scores
__device__ float g_lstm[ROWS*HID];        //  64 MB  lstm_out [S,B,HID]
__device__ float g_h[2][BATCH*HID];       //  h double buffer
__device__ float g_c[BATCH*HID];
__device__ float g_PQ[ROWS*HID];          //  64 MB
__device__ float g_PK[ROWS*HID];
__device__ float g_PV[ROWS*HID];
__device__ unsigned g_cnt;                //  grid barrier counter

// ---------------------------------------------------------------------------
// Helpers
// ---------------------------------------------------------------------------
__device__ __forceinline__ float tf32_rnd(float x) {
    uint32_t u; asm("cvt.rna.tf32.f32 %0, %1;" : "=r"(u) : "f"(x));
    return __uint_as_float(u);
}
__device__ __forceinline__ uint32_t fu(float x) { return __float_as_uint(x); }

#define MMA8(cc, a, bb) \
    asm volatile("mma.sync.aligned.m16n8k8.row.col.f32.tf32.tf32.f32 " \
        "{%0,%1,%2,%3},{%4,%5,%6,%7},{%8,%9},{%0,%1,%2,%3};" \
        : "+f"(cc[0]), "+f"(cc[1]), "+f"(cc[2]), "+f"(cc[3]) \
        : "r"(a[0]), "r"(a[1]), "r"(a[2]), "r"(a[3]), "r"(bb[0]), "r"(bb[1]))

#define CPA16(dst, src) \
    asm volatile("cp.async.cg.shared.global [%0], [%1], 16;" :: "r"(dst), "l"(src))

// ---------------------------------------------------------------------------
// Weight repack: gates (f,i,g,o) interleaved per hid-unit, split x-rows/h-rows
// ---------------------------------------------------------------------------
__global__ void pack_weights(const float* __restrict__ Wf, const float* __restrict__ Wi,
                             const float* __restrict__ Wg, const float* __restrict__ Wo,
                             const float* __restrict__ bf, const float* __restrict__ bi,
                             const float* __restrict__ bg, const float* __restrict__ bo)
{
    int idx = blockIdx.x * blockDim.x + threadIdx.x;   // over 768*512
    if (idx < 768*HID) {
        int k = idx / HID, u = idx % HID;
        float vf = Wf[idx], vi = Wi[idx], vg = Wg[idx], vo = Wo[idx];
        float* dst = (k < D_IN) ? (g_Wxp + (long)k*G4) : (g_Whp + (long)(k - D_IN)*G4);
        dst[u*4+0] = vf; dst[u*4+1] = vi; dst[u*4+2] = vg; dst[u*4+3] = vo;
    }
    if (idx < HID) {
        g_biasp[idx*4+0] = bf[idx];
        g_biasp[idx*4+1] = bi[idx];
        g_biasp[idx*4+2] = bg[idx];
        g_biasp[idx*4+3] = bo[idx];
    }
}

__global__ void zero_state()
{
    int i = blockIdx.x * blockDim.x + threadIdx.x;
    if (i < BATCH*HID) { g_h[0][i] = 0.f; g_c[i] = 0.f; }
    if (i == 0) g_cnt = 0u;
}

// ---------------------------------------------------------------------------
// tf32 3-split GEMM, cp.async double-buffered.
// C = alpha * A @ B(^T) + bias.  A[M,K] row-major.
// transB=0: B[K,N] row-major; transB=1: B[N,K] row-major.
// 64x64 tile, 256 threads (8 warps: wm=(warp>>1)*16, wn=(warp&1)*32).
// Each warp: one m16 row-slab x four n8 tiles. 3 mma passes (hh, hl, lh).
// Raw fp32 staged via cp.async; tf32 hi/lo split at fragment-load time.
// Fragment orders per PTX ISA (validated in R6):
//   A: a0=(r,q) a1=(r+8,q) a2=(r,q+4) a3=(r+8,q+4)
//   B: b0=(k=q,n) b1=(k=q+4,n);  C: (r,2q),(r,2q+1),(r+8,2q),(r+8,2q+1)
// Batched via blockIdx.z: offsets (z>>2)*s1 + (z&3)*s2.
// ---------------------------------------------------------------------------
__global__ __launch_bounds__(256)
void gemm_tf32(const float* __restrict__ A, int lda, long as1, long as2,
               const float* __restrict__ B, int ldb, long bs1, long bs2,
               const float* __restrict__ bias,
               float* __restrict__ C, int ldc, long cs1, long cs2,
               int K, float alpha, int transB)
{
    __shared__ float As[2][64*APITCH];   // 2 x 5120 floats
    __shared__ float Bs[2][64*APITCH];   // sized for trans layout (64x20); normal uses 16x72

    int z = blockIdx.z;
    A += (long)(z >> 2) * as1 + (long)(z & 3) * as2;
    B += (long)(z >> 2) * bs1 + (long)(z & 3) * bs2;
    C += (long)(z >> 2) * cs1 + (long)(z & 3) * cs2;
    int m0 = blockIdx.y * 64, n0 = blockIdx.x * 64;

    int tid = threadIdx.x;
    int warp = tid >> 5, lane = tid & 31;
    int wm = (warp >> 1) * 16, wn = (warp & 1) * 32;
    int r = lane >> 2, q = lane & 3;

    const uint32_t a_smem = (uint32_t)__cvta_generic_to_shared(&As[0][0]);
    const uint32_t b_smem = (uint32_t)__cvta_generic_to_shared(&Bs[0][0]);
    const uint32_t bufstride = 64*APITCH*4;   // bytes per buffer

    // staging indices (one 16B chunk each for A and B per thread per tile)
    int am = tid >> 2, ac = tid & 3;                // A: row 0..63, chunk 0..3
    int bkr = tid >> 4, bc = tid & 15;              // B normal: k-row, n-chunk
    int bn = tid >> 2, bc4 = tid & 3;               // B trans: n-row, k-chunk

    int KT = K >> 4;

    // issue tile kt into buffer kt&1
    auto issue = [&](int kt) {
        int k0 = kt << 4, buf = kt & 1;
        CPA16(a_smem + buf*bufstride + (uint32_t)(am*APITCH + ac*4)*4,
              A + (long)(m0 + am)*lda + k0 + ac*4);
        if (!transB) {
            CPA16(b_smem + buf*bufstride + (uint32_t)(bkr*BPITCH + bc*4)*4,
                  B + (long)(k0 + bkr)*ldb + n0 + bc*4);
        } else {
            CPA16(b_smem + buf*bufstride + (uint32_t)(bn*APITCH + bc4*4)*4,
                  B + (long)(n0 + bn)*ldb + k0 + bc4*4);
        }
        asm volatile("cp.async.commit_group;");
    };

    float acc[4][4];
    #pragma unroll
    for (int nt = 0; nt < 4; nt++)
        #pragma unroll
        for (int e = 0; e < 4; e++) acc[nt][e] = 0.f;

    issue(0);
    for (int kt = 0; kt < KT; kt++) {
        if (kt + 1 < KT) {
            issue(kt + 1);
            asm volatile("cp.async.wait_group 1;" ::: "memory");
        } else {
            asm volatile("cp.async.wait_group 0;" ::: "memory");
        }
        __syncthreads();

        const float* Ab = &As[kt & 1][0];
        const float* Bb = &Bs[kt & 1][0];
        #pragma unroll
        for (int p = 0; p < 2; p++) {
            int kb = p*8;
            int m = wm + r;
            float ar[4];
            ar[0] = Ab[ m     *APITCH + kb+q  ];
            ar[1] = Ab[(m+8)  *APITCH + kb+q  ];
            ar[2] = Ab[ m     *APITCH + kb+q+4];
            ar[3] = Ab[(m+8)  *APITCH + kb+q+4];
            uint32_t ah[4], al[4];
            #pragma unroll
            for (int e = 0; e < 4; e++) {
                float hi = tf32_rnd(ar[e]);
                ah[e] = fu(hi);
                al[e] = fu(tf32_rnd(ar[e] - hi));
            }
            #pragma unroll
            for (int nt = 0; nt < 4; nt++) {
                int n = wn + nt*8 + r;
                float br0, br1;
                if (!transB) {
                    br0 = Bb[(kb+q  )*BPITCH + n];
                    br1 = Bb[(kb+q+4)*BPITCH + n];
                } else {
                    br0 = Bb[n*APITCH + kb+q  ];
                    br1 = Bb[n*APITCH + kb+q+4];
                }
                float bh0f = tf32_rnd(br0), bh1f = tf32_rnd(br1);
                uint32_t bh[2] = { fu(bh0f), fu(bh1f) };
                uint32_t bl[2] = { fu(tf32_rnd(br0 - bh0f)), fu(tf32_rnd(br1 - bh1f)) };
                MMA8(acc[nt], ah, bh);
                MMA8(acc[nt], ah, bl);
                MMA8(acc[nt], al, bh);
            }
        }
        __syncthreads();
    }

    // ---- epilogue ----
    #pragma unroll
    for (int nt = 0; nt < 4; nt++) {
        int mrow = m0 + wm + r;
        int ncol = n0 + wn + nt*8 + q*2;
        float b0 = bias ? bias[ncol]   : 0.f;
        float b1 = bias ? bias[ncol+1] : 0.f;
        C[(long)mrow*ldc + ncol  ]     = alpha*acc[nt][0] + b0;
        C[(long)mrow*ldc + ncol+1]     = alpha*acc[nt][1] + b1;
        C[(long)(mrow+8)*ldc + ncol  ] = alpha*acc[nt][2] + b0;
        C[(long)(mrow+8)*ldc + ncol+1] = alpha*acc[nt][3] + b1;
    }
}

// ---------------------------------------------------------------------------
// Persistent LSTM recurrence (R2 structure — measured inside the 10.32ms run).
// Grid = NB=128 blocks x 256 threads. Block bid owns hid-units [bid*4,bid*4+4)
// (packed cols [bid*16, bid*16+16)). Weight slice resident in SMEM; c in regs;
// h double-buffered in global; device grid barrier per step.
// Barrier arrive: __syncthreads then tid0-only fence+atomicAdd (CG pattern) —
// replaces R2's 256 per-thread __threadfence()s.
// ---------------------------------------------------------------------------
__global__ __launch_bounds__(256)
void lstm_persistent(const float* __restrict__ gx)
{
    extern __shared__ float sm[];
    float* ws = sm;                 // [512][16]  weight slice (32 KB)
    float* hs = sm + HID*16;        // [64][HPAD] staged h     (132 KB)

    int tid = threadIdx.x, bid = blockIdx.x;
    int c0 = bid * 16;

    // preload weight slice: 2048 float4
    #pragma unroll
    for (int i = 0; i < 8; i++) {
        int idx = tid + i*256;
        int k = idx >> 2, j4 = idx & 3;
        float4 w = *(const float4*)(g_Whp + (long)k*G4 + c0 + j4*4);
        *(float4*)(ws + k*16 + j4*4) = w;
    }

    int b = tid >> 2, cq = tid & 3;
    int u = bid*4 + cq;
    float creg = 0.f;
    float* h0 = g_h[0];
    float* h1 = g_h[1];

    __syncthreads();

    for (int t = 0; t < S_LEN; t++) {
        // wait for all blocks to finish step t-1
        if (t) {
            if (tid == 0) {
                unsigned target = (unsigned)t * NB;
                while (*(volatile unsigned*)&g_cnt < target) { }
                __threadfence();
            }
            __syncthreads();
        }

        // stage h_prev (L2 loads: other SMs wrote it) + this step's gx
        const float* hr = (t & 1) ? h1 : h0;
        #pragma unroll 8
        for (int i = 0; i < 32; i++) {
            int idx = tid + i*256;               // float4 index, 8192 total
            int r = idx >> 7, cc = idx & 127;
            float4 v = __ldcg((const float4*)hr + idx);
            *(float4*)(hs + r*HPAD + cc*4) = v;
        }
        float4 gv = *(const float4*)(gx + ((long)t*BATCH + b)*G4 + c0 + cq*4);
        __syncthreads();

        // acc[g] = sum_k h[b][k] * w[k][cq*4+g]
        float ax = 0.f, ay = 0.f, az = 0.f, aw = 0.f;
        const float*  hrow = hs + b*HPAD;
        const float4* wq   = (const float4*)ws + cq;
        #pragma unroll 8
        for (int k = 0; k < HID; k += 4) {
            float4 hv = *(const float4*)(hrow + k);
            float4 w0 = wq[(k+0)*4];
            float4 w1 = wq[(k+1)*4];
            float4 w2 = wq[(k+2)*4];
            float4 w3 = wq[(k+3)*4];
            ax = fmaf(hv.x, w0.x, ax); ay = fmaf(hv.x, w0.y, ay);
            az = fmaf(hv.x, w0.z, az); aw = fmaf(hv.x, w0.w, aw);
            ax = fmaf(hv.y, w1.x, ax); ay = fmaf(hv.y, w1.y, ay);
            az = fmaf(hv.y, w1.z, az); aw = fmaf(hv.y, w1.w, aw);
            ax = fmaf(hv.z, w2.x, ax); ay = fmaf(hv.z, w2.y, ay);
            az = fmaf(hv.z, w2.z, az); aw = fmaf(hv.z, w2.w, aw);
            ax = fmaf(hv.w, w3.x, ax); ay = fmaf(hv.w, w3.y, ay);
            az = fmaf(hv.w, w3.z, az); aw = fmaf(hv.w, w3.w, aw);
        }

        const float* gxr = (const float*)&gv;
        float pf = ax + gxr[0];
        float pi = ay + gxr[1];
        float pg = az + gxr[2];
        float po = aw + gxr[3];
        float f  = 1.f / (1.f + expf(-pf));
        float ii = 1.f / (1.f + expf(-pi));
        float gg = tanhf(pg);
        float o  = 1.f / (1.f + expf(-po));
        creg = f * creg + ii * gg;
        float hn = o * tanhf(creg);

        float* hw = (t & 1) ? h0 : h1;
        hw[b*HID + u] = hn;
        g_lstm[((long)t*BATCH + b)*HID + u] = hn;
        if (t == S_LEN-1) g_c[b*HID + u] = creg;

        // ---- arrive: cta barrier, then tid0-only fence + atomic (CG pattern)
        __syncthreads();
        if (tid == 0) {
            __threadfence();
            atomicAdd(&g_cnt, 1u);
        }
    }
}

// ---------------------------------------------------------------------------
// Row softmax over 512-wide rows. One block (128 threads) per row.
// ---------------------------------------------------------------------------
__global__ __launch_bounds__(128)
void softmax512(float* __restrict__ s)
{
    float* row = s + (size_t)blockIdx.x * 512;
    int tid = threadIdx.x;
    float v0 = row[tid], v1 = row[tid+128], v2 = row[tid+256], v3 = row[tid+384];
    float mx = fmaxf(fmaxf(v0, v1), fmaxf(v2, v3));
    __shared__ float sm[4];
    __shared__ float ss[4];
    #pragma unroll
    for (int off = 16; off > 0; off >>= 1)
        mx = fmaxf(mx, __shfl_xor_sync(0xFFFFFFFFu, mx, off));
    if ((tid & 31) == 0) sm[tid >> 5] = mx;
    __syncthreads();
    mx = fmaxf(fmaxf(sm[0], sm[1]), fmaxf(sm[2], sm[3]));
    v0 = expf(v0 - mx); v1 = expf(v1 - mx); v2 = expf(v2 - mx); v3 = expf(v3 - mx);
    float sum = v0 + v1 + v2 + v3;
    #pragma unroll
    for (int off = 16; off > 0; off >>= 1)
        sum += __shfl_xor_sync(0xFFFFFFFFu, sum, off);
    if ((tid & 31) == 0) ss[tid >> 5] = sum;
    __syncthreads();
    sum = ss[0] + ss[1] + ss[2] + ss[3];
    float inv = 1.f / sum;
    row[tid] = v0*inv; row[tid+128] = v1*inv; row[tid+256] = v2*inv; row[tid+384] = v3*inv;
}

__global__ void copy_hc(const float* __restrict__ h, const float* __restrict__ c,
                        float* __restrict__ out)
{
    int i = blockIdx.x * blockDim.x + threadIdx.x;
    if (i < BATCH*HID) {
        out[DEC_ELEMS + i] = h[i];
        out[DEC_ELEMS + BATCH*HID + i] = c[i];
    }
}

// ---------------------------------------------------------------------------
// Host orchestration (graph-capturable: launches only)
// ---------------------------------------------------------------------------
extern "C" void kernel_launch(void* const* d_in, const int* in_sizes, int n_in,
                              void* d_out, int out_size)
{
    const float* x  = (const float*)d_in[0];
    const float* Wf = (const float*)d_in[1];
    const float* bf = (const float*)d_in[2];
    const float* Wi = (const float*)d_in[3];
    const float* bi = (const float*)d_in[4];
    const float* Wg = (const float*)d_in[5];
    const float* bg = (const float*)d_in[6];
    const float* Wo = (const float*)d_in[7];
    const float* bo = (const float*)d_in[8];
    const float* Wq = (const float*)d_in[9];
    const float* bq = (const float*)d_in[10];
    const float* Wk = (const float*)d_in[11];
    const float* bk = (const float*)d_in[12];
    const float* Wv = (const float*)d_in[13];
    const float* bv = (const float*)d_in[14];
    float* out = (float*)d_out;

    float *Wxp, *biasp, *gx, *lstm, *hbase, *c, *PQ, *PK, *PV;
    cudaGetSymbolAddress((void**)&Wxp,   g_Wxp);
    cudaGetSymbolAddress((void**)&biasp, g_biasp);
    cudaGetSymbolAddress((void**)&gx,    g_gx);
    cudaGetSymbolAddress((void**)&lstm,  g_lstm);
    cudaGetSymbolAddress((void**)&hbase, g_h);
    cudaGetSymbolAddress((void**)&c,     g_c);
    cudaGetSymbolAddress((void**)&PQ,    g_PQ);
    cudaGetSymbolAddress((void**)&PK,    g_PK);
    cudaGetSymbolAddress((void**)&PV,    g_PV);
    float* h0 = hbase;

    const int SMEM_LSTM = (HID*16 + BATCH*HPAD) * (int)sizeof(float);  // 164,864 B
    cudaFuncSetAttribute(lstm_persistent,
                         cudaFuncAttributeMaxDynamicSharedMemorySize, SMEM_LSTM);

    // 1. repack weights + zero h0 / barrier counter
    pack_weights<<<(768*HID + 255)/256, 256>>>(Wf, Wi, Wg, Wo, bf, bi, bg, bo);
    zero_state<<<(BATCH*HID + 255)/256, 256>>>();

    // 2. x-side gate preacts: gx = x @ Wxp + biasp   [32768,256]@[256,2048]
    gemm_tf32<<<dim3(G4/64, ROWS/64, 1), 256>>>(
        x, D_IN, 0, 0, Wxp, G4, 0, 0, biasp, gx, G4, 0, 0, D_IN, 1.0f, 0);

    // 3. recurrence: persistent kernel, device grid barrier per step
    lstm_persistent<<<NB, 256, SMEM_LSTM>>>(gx);

    // 4. Q/K/V projections: [32768,512]@[512,512]+b
    gemm_tf32<<<dim3(HID/64, ROWS/64, 1), 256>>>(
        lstm, HID, 0, 0, Wq, HID, 0, 0, bq, PQ, HID, 0, 0, HID, 1.0f, 0);
    gemm_tf32<<<dim3(HID/64, ROWS/64, 1), 256>>>(
        lstm, HID, 0, 0, Wk, HID, 0, 0, bk, PK, HID, 0, 0, HID, 1.0f, 0);
    gemm_tf32<<<dim3(HID/64, ROWS/64, 1), 256>>>(
        lstm, HID, 0, 0, Wv, HID, 0, 0, bv, PV, HID, 0, 0, HID, 1.0f, 0);

    // 5. scores = (Q @ K^T)/sqrt(dk), z = b'*4 + h
    const long pbS = (long)S_LEN * HID;          // per-b' stride in PQ/PK/PV
    const long phS = DK;                         // per-h stride
    const long scB = 4L * S_LEN * S_LEN;         // scores per-b' stride
    const long scH = (long)S_LEN * S_LEN;        // scores per-h stride
    float scale = 1.0f / sqrtf((float)DK);
    gemm_tf32<<<dim3(S_LEN/64, S_LEN/64, BATCH*NH), 256>>>(
        PQ, HID, pbS, phS,
        PK, HID, pbS, phS,
        (const float*)0,
        gx /* reused as scores */, S_LEN, scB, scH, DK, scale, 1);

    // 6. softmax over last axis
    softmax512<<<BATCH*NH*S_LEN, 128>>>(gx);

    // 7. out = attn @ V, written directly in decoded layout:
    //    d_out[(s*64 + b')*512 + h*128 + d]
    gemm_tf32<<<dim3(DK/64, S_LEN/64, BATCH*NH), 256>>>(
        gx, S_LEN, scB, scH,
        PV, HID, pbS, phS,
        (const float*)0,
        out, BATCH*HID, (long)HID, (long)DK, S_LEN, 1.0f, 0);

    // 8. final hidden/cell state (after step 511 the live h buffer is h0)
    copy_hc<<<(BATCH*HID + 255)/256, 256>>>(h0, c, out);
}

// round 8
// speedup vs baseline: 1.9486x; 1.2147x over previous
#include <cuda_runtime.h>
#include <math.h>
#include <stdint.h>

// ---------------------------------------------------------------------------
// Problem constants
// ---------------------------------------------------------------------------
#define S_LEN   512
#define BATCH   64
#define D_IN    256
#define HID     512
#define G4      2048        // 4 gates * HID, packed unit-major: col = u*4 + gate
#define NH      4
#define DK      128
#define ROWS    (S_LEN*BATCH)        // 32768
#define DEC_ELEMS (S_LEN*BATCH*HID)  // 16777216
#define NB      128                  // persistent LSTM blocks
#define HPAD    516                  // padded pitch (floats): 4r+q bank map, conflict-free
#define APITCH  20                   // gemm A-smem pitch (floats)
#define BPITCH  72                   // gemm B-smem pitch, normal path

// ---------------------------------------------------------------------------
// Device scratch (static allocations only — no cudaMalloc allowed)
// ---------------------------------------------------------------------------
__device__ float g_Wxp[D_IN*G4];          //   2 MB  packed input-gate weights
__device__ float g_Whp[HID*G4];           //   4 MB  packed recurrent-gate weights
__device__ float g_biasp[G4];
__device__ float g_gx[ROWS*G4];           // 256 MB  x-side gate preacts; reused as attn scores
__device__ float g_lstm[ROWS*HID];        //  64 MB  lstm_out [S,B,HID]
__device__ float g_h[2][BATCH*HID];       //  h double buffer
__device__ float g_c[BATCH*HID];
__device__ float g_PQ[ROWS*HID];          //  64 MB
__device__ float g_PK[ROWS*HID];
__device__ float g_PV[ROWS*HID];
__device__ unsigned g_cnt;                //  grid barrier counter

// ---------------------------------------------------------------------------
// Helpers
// ---------------------------------------------------------------------------
__device__ __forceinline__ float tf32_rnd(float x) {
    uint32_t u; asm("cvt.rna.tf32.f32 %0, %1;" : "=r"(u) : "f"(x));
    return __uint_as_float(u);
}
__device__ __forceinline__ uint32_t fu(float x) { return __float_as_uint(x); }

#define MMA8(cc, a, bb) \
    asm volatile("mma.sync.aligned.m16n8k8.row.col.f32.tf32.tf32.f32 " \
        "{%0,%1,%2,%3},{%4,%5,%6,%7},{%8,%9},{%0,%1,%2,%3};" \
        : "+f"(cc[0]), "+f"(cc[1]), "+f"(cc[2]), "+f"(cc[3]) \
        : "r"(a[0]), "r"(a[1]), "r"(a[2]), "r"(a[3]), "r"(bb[0]), "r"(bb[1]))

#define CPA16(dst, src) \
    asm volatile("cp.async.cg.shared.global [%0], [%1], 16;" :: "r"(dst), "l"(src))

// ---------------------------------------------------------------------------
// Weight repack: gates (f,i,g,o) interleaved per hid-unit, split x-rows/h-rows
// ---------------------------------------------------------------------------
__global__ void pack_weights(const float* __restrict__ Wf, const float* __restrict__ Wi,
                             const float* __restrict__ Wg, const float* __restrict__ Wo,
                             const float* __restrict__ bf, const float* __restrict__ bi,
                             const float* __restrict__ bg, const float* __restrict__ bo)
{
    int idx = blockIdx.x * blockDim.x + threadIdx.x;   // over 768*512
    if (idx < 768*HID) {
        int k = idx / HID, u = idx % HID;
        float vf = Wf[idx], vi = Wi[idx], vg = Wg[idx], vo = Wo[idx];
        float* dst = (k < D_IN) ? (g_Wxp + (long)k*G4) : (g_Whp + (long)(k - D_IN)*G4);
        dst[u*4+0] = vf; dst[u*4+1] = vi; dst[u*4+2] = vg; dst[u*4+3] = vo;
    }
    if (idx < HID) {
        g_biasp[idx*4+0] = bf[idx];
        g_biasp[idx*4+1] = bi[idx];
        g_biasp[idx*4+2] = bg[idx];
        g_biasp[idx*4+3] = bo[idx];
    }
}

__global__ void zero_state()
{
    int i = blockIdx.x * blockDim.x + threadIdx.x;
    if (i < BATCH*HID) { g_h[0][i] = 0.f; g_c[i] = 0.f; }
    if (i == 0) g_cnt = 0u;
}

// ---------------------------------------------------------------------------
// tf32 3-split GEMM, cp.async double-buffered (unchanged from R7).
// ---------------------------------------------------------------------------
__global__ __launch_bounds__(256)
void gemm_tf32(const float* __restrict__ A, int lda, long as1, long as2,
               const float* __restrict__ B, int ldb, long bs1, long bs2,
               const float* __restrict__ bias,
               float* __restrict__ C, int ldc, long cs1, long cs2,
               int K, float alpha, int transB)
{
    __shared__ float As[2][64*APITCH];
    __shared__ float Bs[2][64*APITCH];

    int z = blockIdx.z;
    A += (long)(z >> 2) * as1 + (long)(z & 3) * as2;
    B += (long)(z >> 2) * bs1 + (long)(z & 3) * bs2;
    C += (long)(z >> 2) * cs1 + (long)(z & 3) * cs2;
    int m0 = blockIdx.y * 64, n0 = blockIdx.x * 64;

    int tid = threadIdx.x;
    int warp = tid >> 5, lane = tid & 31;
    int wm = (warp >> 1) * 16, wn = (warp & 1) * 32;
    int r = lane >> 2, q = lane & 3;

    const uint32_t a_smem = (uint32_t)__cvta_generic_to_shared(&As[0][0]);
    const uint32_t b_smem = (uint32_t)__cvta_generic_to_shared(&Bs[0][0]);
    const uint32_t bufstride = 64*APITCH*4;

    int am = tid >> 2, ac = tid & 3;
    int bkr = tid >> 4, bc = tid & 15;
    int bn = tid >> 2, bc4 = tid & 3;

    int KT = K >> 4;

    auto issue = [&](int kt) {
        int k0 = kt << 4, buf = kt & 1;
        CPA16(a_smem + buf*bufstride + (uint32_t)(am*APITCH + ac*4)*4,
              A + (long)(m0 + am)*lda + k0 + ac*4);
        if (!transB) {
            CPA16(b_smem + buf*bufstride + (uint32_t)(bkr*BPITCH + bc*4)*4,
                  B + (long)(k0 + bkr)*ldb + n0 + bc*4);
        } else {
            CPA16(b_smem + buf*bufstride + (uint32_t)(bn*APITCH + bc4*4)*4,
                  B + (long)(n0 + bn)*ldb + k0 + bc4*4);
        }
        asm volatile("cp.async.commit_group;");
    };

    float acc[4][4];
    #pragma unroll
    for (int nt = 0; nt < 4; nt++)
        #pragma unroll
        for (int e = 0; e < 4; e++) acc[nt][e] = 0.f;

    issue(0);
    for (int kt = 0; kt < KT; kt++) {
        if (kt + 1 < KT) {
            issue(kt + 1);
            asm volatile("cp.async.wait_group 1;" ::: "memory");
        } else {
            asm volatile("cp.async.wait_group 0;" ::: "memory");
        }
        __syncthreads();

        const float* Ab = &As[kt & 1][0];
        const float* Bb = &Bs[kt & 1][0];
        #pragma unroll
        for (int p = 0; p < 2; p++) {
            int kb = p*8;
            int m = wm + r;
            float ar[4];
            ar[0] = Ab[ m     *APITCH + kb+q  ];
            ar[1] = Ab[(m+8)  *APITCH + kb+q  ];
            ar[2] = Ab[ m     *APITCH + kb+q+4];
            ar[3] = Ab[(m+8)  *APITCH + kb+q+4];
            uint32_t ah[4], al[4];
            #pragma unroll
            for (int e = 0; e < 4; e++) {
                float hi = tf32_rnd(ar[e]);
                ah[e] = fu(hi);
                al[e] = fu(tf32_rnd(ar[e] - hi));
            }
            #pragma unroll
            for (int nt = 0; nt < 4; nt++) {
                int n = wn + nt*8 + r;
                float br0, br1;
                if (!transB) {
                    br0 = Bb[(kb+q  )*BPITCH + n];
                    br1 = Bb[(kb+q+4)*BPITCH + n];
                } else {
                    br0 = Bb[n*APITCH + kb+q  ];
                    br1 = Bb[n*APITCH + kb+q+4];
                }
                float bh0f = tf32_rnd(br0), bh1f = tf32_rnd(br1);
                uint32_t bh[2] = { fu(bh0f), fu(bh1f) };
                uint32_t bl[2] = { fu(tf32_rnd(br0 - bh0f)), fu(tf32_rnd(br1 - bh1f)) };
                MMA8(acc[nt], ah, bh);
                MMA8(acc[nt], ah, bl);
                MMA8(acc[nt], al, bh);
            }
        }
        __syncthreads();
    }

    #pragma unroll
    for (int nt = 0; nt < 4; nt++) {
        int mrow = m0 + wm + r;
        int ncol = n0 + wn + nt*8 + q*2;
        float b0 = bias ? bias[ncol]   : 0.f;
        float b1 = bias ? bias[ncol+1] : 0.f;
        C[(long)mrow*ldc + ncol  ]     = alpha*acc[nt][0] + b0;
        C[(long)mrow*ldc + ncol+1]     = alpha*acc[nt][1] + b1;
        C[(long)(mrow+8)*ldc + ncol  ] = alpha*acc[nt][2] + b0;
        C[(long)(mrow+8)*ldc + ncol+1] = alpha*acc[nt][3] + b1;
    }
}

// ---------------------------------------------------------------------------
// Persistent LSTM recurrence — TENSOR-CORE matvec version.
// Grid = NB=128 blocks x 256 threads (8 warps). Block bid owns packed cols
// [bid*16, bid*16+16) = hid-units [bid*4, bid*4+4) x 4 gates.
// Per step: out[64x16] = h[64x512] @ Wslice[512x16] via m16n8k8 tf32 3-split.
// Warp w -> tile (mt = w>>1 in 0..3, nt = w&1): rows [mt*16, +16), cols [nt*8, +8).
// Weights presplit (hi/lo tf32) ONCE into n-major smem [j][k], pitch 516.
// h staged raw fp32 each step into smem [row][k], pitch 516 (both conflict-free:
// bank = 4*low + q covers all 32).
// Epilogue: C frag (r,2q),(r,2q+1),(r+8,2q),(r+8,2q+1); even-q lanes hold (f,i),
// odd-q hold (g,o) of unit (q>>1)+2nt; one shfl.xor(1) exchange; c in registers.
// Grid barrier: tid0 spin + __syncthreads / syncthreads + tid0 fence+atomicAdd.
// ---------------------------------------------------------------------------
__global__ __launch_bounds__(256)
void lstm_persistent(const float* __restrict__ gx)
{
    extern __shared__ float sm[];
    float* Bhs = sm;                    // [16][516] presplit weight hi
    float* Bls = sm + 16*HPAD;          // [16][516] presplit weight lo
    float* hs  = sm + 32*HPAD;          // [64][516] staged h

    const int tid = threadIdx.x, bid = blockIdx.x;
    const int c0 = bid * 16;
    const int warp = tid >> 5, lane = tid & 31;
    const int mt = warp >> 1, nt = warp & 1;
    const int r = lane >> 2, q = lane & 3;
    const int row0 = mt*16 + r;                 // second row = row0 + 8

    // ---- presplit weight slice into n-major hi/lo (once) ----
    for (int idx = tid; idx < 16*512; idx += 256) {
        int k = idx >> 4, j = idx & 15;
        float w = g_Whp[(long)k*G4 + c0 + j];
        float hi = tf32_rnd(w);
        Bhs[j*HPAD + k] = hi;
        Bls[j*HPAD + k] = tf32_rnd(w - hi);
    }

    float c_a = 0.f, c_b = 0.f;                 // cell state (even-q lanes)
    float* h0 = g_h[0];
    float* h1 = g_h[1];
    const int u = bid*4 + nt*2 + (q >> 1);      // global hid-unit (even-q lanes)

    __syncthreads();

    const float* arow0 = hs + row0*HPAD;
    const float* arow8 = arow0 + 8*HPAD;
    const float* brh   = Bhs + (nt*8 + r)*HPAD;
    const float* brl   = Bls + (nt*8 + r)*HPAD;

    for (int t = 0; t < S_LEN; t++) {
        // prefetch this thread's 4 gx preacts (cols 2q, 2q+1 of rows row0, row0+8)
        const float* gbase = gx + ((long)t*BATCH)*G4 + c0 + nt*8 + 2*q;
        const float2 gA = *(const float2*)(gbase + (long)row0*G4);
        const float2 gB = *(const float2*)(gbase + (long)(row0+8)*G4);

        // ---- grid barrier: wait for all blocks to finish step t-1 ----
        if (t) {
            if (tid == 0) {
                unsigned target = (unsigned)t * NB;
                while (*(volatile unsigned*)&g_cnt < target) { }
                __threadfence();
            }
            __syncthreads();
        }

        // ---- stage h_prev into smem ----
        const float* hr = (t & 1) ? h1 : h0;
        #pragma unroll 8
        for (int i = 0; i < 32; i++) {
            int idx = tid + i*256;               // float4 index, 8192 total
            int rr = idx >> 7, cc = idx & 127;
            float4 v = __ldcg((const float4*)hr + idx);
            *(float4*)(hs + rr*HPAD + cc*4) = v;
        }
        __syncthreads();

        // ---- 64x16 = h @ Wslice via tensor cores (3-split tf32) ----
        float acc[4] = {0.f, 0.f, 0.f, 0.f};
        #pragma unroll 4
        for (int k0 = 0; k0 < HID; k0 += 8) {
            float a0 = arow0[k0+q  ];
            float a1 = arow8[k0+q  ];
            float a2 = arow0[k0+q+4];
            float a3 = arow8[k0+q+4];
            float h0f = tf32_rnd(a0), h1f = tf32_rnd(a1);
            float h2f = tf32_rnd(a2), h3f = tf32_rnd(a3);
            uint32_t ah[4] = { fu(h0f), fu(h1f), fu(h2f), fu(h3f) };
            uint32_t al[4] = { fu(tf32_rnd(a0 - h0f)), fu(tf32_rnd(a1 - h1f)),
                               fu(tf32_rnd(a2 - h2f)), fu(tf32_rnd(a3 - h3f)) };
            uint32_t bh[2] = { fu(brh[k0+q]), fu(brh[k0+q+4]) };
            uint32_t bl[2] = { fu(brl[k0+q]), fu(brl[k0+q+4]) };
            MMA8(acc, ah, bh);
            MMA8(acc, ah, bl);
            MMA8(acc, al, bh);
        }

        // ---- epilogue: add gx, activate, exchange, cell update ----
        float p0 = acc[0] + gA.x;   // (row0,   2q)
        float p1 = acc[1] + gA.y;   // (row0,   2q+1)
        float p2 = acc[2] + gB.x;   // (row0+8, 2q)
        float p3 = acc[3] + gB.y;   // (row0+8, 2q+1)

        float s0, s1, s2, s3;
        if (q & 1) {                // odd lanes: cols are (g, o)
            s0 = tanhf(p0);
            s1 = 1.f / (1.f + expf(-p1));
            s2 = tanhf(p2);
            s3 = 1.f / (1.f + expf(-p3));
        } else {                    // even lanes: cols are (f, i)
            s0 = 1.f / (1.f + expf(-p0));
            s1 = 1.f / (1.f + expf(-p1));
            s2 = 1.f / (1.f + expf(-p2));
            s3 = 1.f / (1.f + expf(-p3));
        }
        float x0 = __shfl_xor_sync(0xFFFFFFFFu, s0, 1);   // partner's g (for even)
        float x1 = __shfl_xor_sync(0xFFFFFFFFu, s1, 1);   // partner's o
        float x2 = __shfl_xor_sync(0xFFFFFFFFu, s2, 1);
        float x3 = __shfl_xor_sync(0xFFFFFFFFu, s3, 1);

        if (!(q & 1)) {
            // s0=f, s1=i, x0=g, x1=o  (row0);  s2,s3,x2,x3 for row0+8
            c_a = s0 * c_a + s1 * x0;
            float hA = x1 * tanhf(c_a);
            c_b = s2 * c_b + s3 * x2;
            float hB = x3 * tanhf(c_b);

            float* hw = (t & 1) ? h0 : h1;
            hw[row0*HID + u] = hA;
            hw[(row0+8)*HID + u] = hB;
            g_lstm[((long)t*BATCH + row0)*HID + u] = hA;
            g_lstm[((long)t*BATCH + row0+8)*HID + u] = hB;
            if (t == S_LEN-1) {
                g_c[row0*HID + u] = c_a;
                g_c[(row0+8)*HID + u] = c_b;
            }
        }

        // ---- arrive: cta barrier, then tid0-only fence + atomic ----
        __syncthreads();
        if (tid == 0) {
            __threadfence();
            atomicAdd(&g_cnt, 1u);
        }
    }
}

// ---------------------------------------------------------------------------
// Row softmax over 512-wide rows. One block (128 threads) per row.
// ---------------------------------------------------------------------------
__global__ __launch_bounds__(128)
void softmax512(float* __restrict__ s)
{
    float* row = s + (size_t)blockIdx.x * 512;
    int tid = threadIdx.x;
    float v0 = row[tid], v1 = row[tid+128], v2 = row[tid+256], v3 = row[tid+384];
    float mx = fmaxf(fmaxf(v0, v1), fmaxf(v2, v3));
    __shared__ float sm[4];
    __shared__ float ss[4];
    #pragma unroll
    for (int off = 16; off > 0; off >>= 1)
        mx = fmaxf(mx, __shfl_xor_sync(0xFFFFFFFFu, mx, off));
    if ((tid & 31) == 0) sm[tid >> 5] = mx;
    __syncthreads();
    mx = fmaxf(fmaxf(sm[0], sm[1]), fmaxf(sm[2], sm[3]));
    v0 = expf(v0 - mx); v1 = expf(v1 - mx); v2 = expf(v2 - mx); v3 = expf(v3 - mx);
    float sum = v0 + v1 + v2 + v3;
    #pragma unroll
    for (int off = 16; off > 0; off >>= 1)
        sum += __shfl_xor_sync(0xFFFFFFFFu, sum, off);
    if ((tid & 31) == 0) ss[tid >> 5] = sum;
    __syncthreads();
    sum = ss[0] + ss[1] + ss[2] + ss[3];
    float inv = 1.f / sum;
    row[tid] = v0*inv; row[tid+128] = v1*inv; row[tid+256] = v2*inv; row[tid+384] = v3*inv;
}

__global__ void copy_hc(const float* __restrict__ h, const float* __restrict__ c,
                        float* __restrict__ out)
{
    int i = blockIdx.x * blockDim.x + threadIdx.x;
    if (i < BATCH*HID) {
        out[DEC_ELEMS + i] = h[i];
        out[DEC_ELEMS + BATCH*HID + i] = c[i];
    }
}

// ---------------------------------------------------------------------------
// Host orchestration (graph-capturable: launches only)
// ---------------------------------------------------------------------------
extern "C" void kernel_launch(void* const* d_in, const int* in_sizes, int n_in,
                              void* d_out, int out_size)
{
    const float* x  = (const float*)d_in[0];
    const float* Wf = (const float*)d_in[1];
    const float* bf = (const float*)d_in[2];
    const float* Wi = (const float*)d_in[3];
    const float* bi = (const float*)d_in[4];
    const float* Wg = (const float*)d_in[5];
    const float* bg = (const float*)d_in[6];
    const float* Wo = (const float*)d_in[7];
    const float* bo = (const float*)d_in[8];
    const float* Wq = (const float*)d_in[9];
    const float* bq = (const float*)d_in[10];
    const float* Wk = (const float*)d_in[11];
    const float* bk = (const float*)d_in[12];
    const float* Wv = (const float*)d_in[13];
    const float* bv = (const float*)d_in[14];
    float* out = (float*)d_out;

    float *Wxp, *biasp, *gx, *lstm, *hbase, *c, *PQ, *PK, *PV;
    cudaGetSymbolAddress((void**)&Wxp,   g_Wxp);
    cudaGetSymbolAddress((void**)&biasp, g_biasp);
    cudaGetSymbolAddress((void**)&gx,    g_gx);
    cudaGetSymbolAddress((void**)&lstm,  g_lstm);
    cudaGetSymbolAddress((void**)&hbase, g_h);
    cudaGetSymbolAddress((void**)&c,     g_c);
    cudaGetSymbolAddress((void**)&PQ,    g_PQ);
    cudaGetSymbolAddress((void**)&PK,    g_PK);
    cudaGetSymbolAddress((void**)&PV,    g_PV);
    float* h0 = hbase;

    // smem: (16 + 16 + 64) * 516 floats = 198,144 B
    const int SMEM_LSTM = (96*HPAD) * (int)sizeof(float);
    cudaFuncSetAttribute(lstm_persistent,
                         cudaFuncAttributeMaxDynamicSharedMemorySize, SMEM_LSTM);

    // 1. repack weights + zero h0 / barrier counter
    pack_weights<<<(768*HID + 255)/256, 256>>>(Wf, Wi, Wg, Wo, bf, bi, bg, bo);
    zero_state<<<(BATCH*HID + 255)/256, 256>>>();

    // 2. x-side gate preacts: gx = x @ Wxp + biasp   [32768,256]@[256,2048]
    gemm_tf32<<<dim3(G4/64, ROWS/64, 1), 256>>>(
        x, D_IN, 0, 0, Wxp, G4, 0, 0, biasp, gx, G4, 0, 0, D_IN, 1.0f, 0);

    // 3. recurrence: persistent tensor-core kernel, device grid barrier per step
    lstm_persistent<<<NB, 256, SMEM_LSTM>>>(gx);

    // 4. Q/K/V projections: [32768,512]@[512,512]+b
    gemm_tf32<<<dim3(HID/64, ROWS/64, 1), 256>>>(
        lstm, HID, 0, 0, Wq, HID, 0, 0, bq, PQ, HID, 0, 0, HID, 1.0f, 0);
    gemm_tf32<<<dim3(HID/64, ROWS/64, 1), 256>>>(
        lstm, HID, 0, 0, Wk, HID, 0, 0, bk, PK, HID, 0, 0, HID, 1.0f, 0);
    gemm_tf32<<<dim3(HID/64, ROWS/64, 1), 256>>>(
        lstm, HID, 0, 0, Wv, HID, 0, 0, bv, PV, HID, 0, 0, HID, 1.0f, 0);

    // 5. scores = (Q @ K^T)/sqrt(dk), z = b'*4 + h
    const long pbS = (long)S_LEN * HID;          // per-b' stride in PQ/PK/PV
    const long phS = DK;                         // per-h stride
    const long scB = 4L * S_LEN * S_LEN;         // scores per-b' stride
    const long scH = (long)S_LEN * S_LEN;        // scores per-h stride
    float scale = 1.0f / sqrtf((float)DK);
    gemm_tf32<<<dim3(S_LEN/64, S_LEN/64, BATCH*NH), 256>>>(
        PQ, HID, pbS, phS,
        PK, HID, pbS, phS,
        (const float*)0,
        gx /* reused as scores */, S_LEN, scB, scH, DK, scale, 1);

    // 6. softmax over last axis
    softmax512<<<BATCH*NH*S_LEN, 128>>>(gx);

    // 7. out = attn @ V, written directly in decoded layout:
    //    d_out[(s*64 + b')*512 + h*128 + d]
    gemm_tf32<<<dim3(DK/64, S_LEN/64, BATCH*NH), 256>>>(
        gx, S_LEN, scB, scH,
        PV, HID, pbS, phS,
        (const float*)0,
        out, BATCH*HID, (long)HID, (long)DK, S_LEN, 1.0f, 0);

    // 8. final hidden/cell state (after step 511 the live h buffer is h0)
    copy_hc<<<(BATCH*HID + 255)/256, 256>>>(h0, c, out);
}

// round 10
// speedup vs baseline: 2.0511x; 1.0526x over previous
#include <cuda_runtime.h>
#include <math.h>
#include <stdint.h>

// ---------------------------------------------------------------------------
// Problem constants
// ---------------------------------------------------------------------------
#define S_LEN   512
#define BATCH   64
#define D_IN    256
#define HID     512
#define G4      2048        // 4 gates * HID, packed unit-major: col = u*4 + gate
#define NH      4
#define DK      128
#define ROWS    (S_LEN*BATCH)        // 32768
#define DEC_ELEMS (S_LEN*BATCH*HID)  // 16777216
#define NB      128                  // persistent LSTM blocks
#define HPAD    516                  // padded pitch (floats)
#define APITCH  20                   // gemm A-smem pitch (floats)
#define BPITCH  72                   // gemm B-smem pitch, normal path
#define BTFL    1280                 // gemm B buffer floats (max of 16*72, 64*20)

// ---------------------------------------------------------------------------
// Device scratch (static allocations only — no cudaMalloc allowed)
// ---------------------------------------------------------------------------
__device__ float g_Wxp[D_IN*G4];          //   2 MB  packed input-gate weights
__device__ float g_Whp[HID*G4];           //   4 MB  packed recurrent-gate weights
__device__ float g_biasp[G4];
__device__ float g_gx[ROWS*G4];           // 256 MB  x-side gate preacts; reused as attn scores
__device__ float g_lstm[ROWS*HID];        //  64 MB  lstm_out [S,B,HID]
__device__ float g_h[2][BATCH*HID];       //  h double buffer
__device__ float g_c[BATCH*HID];
__device__ float g_PQ[ROWS*HID];          //  64 MB
__device__ float g_PK[ROWS*HID];
__device__ float g_PV[ROWS*HID];
__device__ unsigned g_cnt;                //  grid barrier counter

// ---------------------------------------------------------------------------
// Helpers
// ---------------------------------------------------------------------------
__device__ __forceinline__ float tf32_rnd(float x) {
    uint32_t u; asm("cvt.rna.tf32.f32 %0, %1;" : "=r"(u) : "f"(x));
    return __uint_as_float(u);
}
__device__ __forceinline__ uint32_t fu(float x) { return __float_as_uint(x); }

#define MMA8(cc, a, bb) \
    asm volatile("mma.sync.aligned.m16n8k8.row.col.f32.tf32.tf32.f32 " \
        "{%0,%1,%2,%3},{%4,%5,%6,%7},{%8,%9},{%0,%1,%2,%3};" \
        : "+f"(cc[0]), "+f"(cc[1]), "+f"(cc[2]), "+f"(cc[3]) \
        : "r"(a[0]), "r"(a[1]), "r"(a[2]), "r"(a[3]), "r"(bb[0]), "r"(bb[1]))

#define CPA16(dst, src) \
    asm volatile("cp.async.cg.shared.global [%0], [%1], 16;" :: "r"(dst), "l"(src))

// ---------------------------------------------------------------------------
// Weight repack: gates (f,i,g,o) interleaved per hid-unit, split x-rows/h-rows
// ---------------------------------------------------------------------------
__global__ void pack_weights(const float* __restrict__ Wf, const float* __restrict__ Wi,
                             const float* __restrict__ Wg, const float* __restrict__ Wo,
                             const float* __restrict__ bf, const float* __restrict__ bi,
                             const float* __restrict__ bg, const float* __restrict__ bo)
{
    int idx = blockIdx.x * blockDim.x + threadIdx.x;   // over 768*512
    if (idx < 768*HID) {
        int k = idx / HID, u = idx % HID;
        float vf = Wf[idx], vi = Wi[idx], vg = Wg[idx], vo = Wo[idx];
        float* dst = (k < D_IN) ? (g_Wxp + (long)k*G4) : (g_Whp + (long)(k - D_IN)*G4);
        dst[u*4+0] = vf; dst[u*4+1] = vi; dst[u*4+2] = vg; dst[u*4+3] = vo;
    }
    if (idx < HID) {
        g_biasp[idx*4+0] = bf[idx];
        g_biasp[idx*4+1] = bi[idx];
        g_biasp[idx*4+2] = bg[idx];
        g_biasp[idx*4+3] = bo[idx];
    }
}

__global__ void zero_state()
{
    int i = blockIdx.x * blockDim.x + threadIdx.x;
    if (i < BATCH*HID) { g_h[0][i] = 0.f; g_c[i] = 0.f; }
    if (i == 0) g_cnt = 0u;
}

// ---------------------------------------------------------------------------
// tf32 3-split GEMM v3: 128x64 block tile, 256 threads, 2 blocks/SM.
// C = alpha * A @ B(^T) + bias.  A[M,K] row-major (M % 128 == 0).
// transB=0: B[K,N] row-major; transB=1: B[N,K] row-major.
// 8 warps: warp -> wm=(warp>>1)*32, wn=(warp&1)*32; each warp 32x32 =
// 2 m16-subtiles x 4 n8-subtiles, m16n8k8 tf32, 3 passes (hh, hl, lh).
// cp.async double-buffered k16 tiles; raw fp32 staged, split at frag load.
// Fragment orders (validated R6-R8):
//   A: a0=(r,q) a1=(r+8,q) a2=(r,q+4) a3=(r+8,q+4)
//   B: b0=(k=q,n) b1=(k=q+4,n);  C: (r,2q),(r,2q+1),(r+8,2q),(r+8,2q+1)
// Batched via blockIdx.z: offsets (z>>2)*s1 + (z&3)*s2.
// ---------------------------------------------------------------------------
__global__ __launch_bounds__(256, 2)
void gemm_tf32(const float* __restrict__ A, int lda, long as1, long as2,
               const float* __restrict__ B, int ldb, long bs1, long bs2,
               const float* __restrict__ bias,
               float* __restrict__ C, int ldc, long cs1, long cs2,
               int K, float alpha, int transB)
{
    __shared__ float As[2][128*APITCH];   // 2 x 2560 floats
    __shared__ float Bs[2][BTFL];         // normal: 16x72; trans: 64x20

    int z = blockIdx.z;
    A += (long)(z >> 2) * as1 + (long)(z & 3) * as2;
    B += (long)(z >> 2) * bs1 + (long)(z & 3) * bs2;
    C += (long)(z >> 2) * cs1 + (long)(z & 3) * cs2;
    int m0 = blockIdx.y * 128, n0 = blockIdx.x * 64;

    int tid = threadIdx.x;
    int warp = tid >> 5, lane = tid & 31;
    int wm = (warp >> 1) * 32, wn = (warp & 1) * 32;
    int r = lane >> 2, q = lane & 3;

    const uint32_t a_smem = (uint32_t)__cvta_generic_to_shared(&As[0][0]);
    const uint32_t b_smem = (uint32_t)__cvta_generic_to_shared(&Bs[0][0]);
    const uint32_t abuf = 128*APITCH*4;
    const uint32_t bbuf = BTFL*4;

    // staging indices: A = 512 float4 (2/thread), B = 256 float4 (1/thread)
    int am0 = tid >> 2, ac = tid & 3;               // A row (0..63 | +64), k-chunk
    int bkr = tid >> 4, bc = tid & 15;              // B normal: k-row, n-chunk
    int bn = tid >> 2, bc4 = tid & 3;               // B trans: n-row, k-chunk

    int KT = K >> 4;

    auto issue = [&](int kt) {
        int k0 = kt << 4, buf = kt & 1;
        CPA16(a_smem + buf*abuf + (uint32_t)(am0*APITCH + ac*4)*4,
              A + (long)(m0 + am0)*lda + k0 + ac*4);
        CPA16(a_smem + buf*abuf + (uint32_t)((am0+64)*APITCH + ac*4)*4,
              A + (long)(m0 + am0 + 64)*lda + k0 + ac*4);
        if (!transB) {
            CPA16(b_smem + buf*bbuf + (uint32_t)(bkr*BPITCH + bc*4)*4,
                  B + (long)(k0 + bkr)*ldb + n0 + bc*4);
        } else {
            CPA16(b_smem + buf*bbuf + (uint32_t)(bn*APITCH + bc4*4)*4,
                  B + (long)(n0 + bn)*ldb + k0 + bc4*4);
        }
        asm volatile("cp.async.commit_group;");
    };

    float acc[2][4][4];
    #pragma unroll
    for (int mt = 0; mt < 2; mt++)
        #pragma unroll
        for (int nt = 0; nt < 4; nt++)
            #pragma unroll
            for (int e = 0; e < 4; e++) acc[mt][nt][e] = 0.f;

    issue(0);
    for (int kt = 0; kt < KT; kt++) {
        if (kt + 1 < KT) {
            issue(kt + 1);
            asm volatile("cp.async.wait_group 1;" ::: "memory");
        } else {
            asm volatile("cp.async.wait_group 0;" ::: "memory");
        }
        __syncthreads();

        const float* Ab = &As[kt & 1][0];
        const float* Bb = &Bs[kt & 1][0];
        #pragma unroll
        for (int p = 0; p < 2; p++) {
            int kb = p*8;
            // ---- B frags (shared across both m-subtiles) ----
            uint32_t bh[4][2], bl[4][2];
            #pragma unroll
            for (int nt = 0; nt < 4; nt++) {
                int n = wn + nt*8 + r;
                float br0, br1;
                if (!transB) {
                    br0 = Bb[(kb+q  )*BPITCH + n];
                    br1 = Bb[(kb+q+4)*BPITCH + n];
                } else {
                    br0 = Bb[n*APITCH + kb+q  ];
                    br1 = Bb[n*APITCH + kb+q+4];
                }
                float bh0f = tf32_rnd(br0), bh1f = tf32_rnd(br1);
                bh[nt][0] = fu(bh0f);            bh[nt][1] = fu(bh1f);
                bl[nt][0] = fu(tf32_rnd(br0 - bh0f));
                bl[nt][1] = fu(tf32_rnd(br1 - bh1f));
            }
            // ---- A frags + MMAs per m-subtile ----
            #pragma unroll
            for (int mt = 0; mt < 2; mt++) {
                int m = wm + mt*16 + r;
                float ar[4];
                ar[0] = Ab[ m     *APITCH + kb+q  ];
                ar[1] = Ab[(m+8)  *APITCH + kb+q  ];
                ar[2] = Ab[ m     *APITCH + kb+q+4];
                ar[3] = Ab[(m+8)  *APITCH + kb+q+4];
                uint32_t ah[4], al[4];
                #pragma unroll
                for (int e = 0; e < 4; e++) {
                    float hi = tf32_rnd(ar[e]);
                    ah[e] = fu(hi);
                    al[e] = fu(tf32_rnd(ar[e] - hi));
                }
                #pragma unroll
                for (int nt = 0; nt < 4; nt++) {
                    MMA8(acc[mt][nt], ah, bh[nt]);
                    MMA8(acc[mt][nt], ah, bl[nt]);
                    MMA8(acc[mt][nt], al, bh[nt]);
                }
            }
        }
        __syncthreads();
    }

    // ---- epilogue ----
    #pragma unroll
    for (int mt = 0; mt < 2; mt++)
        #pragma unroll
        for (int nt = 0; nt < 4; nt++) {
            int mrow = m0 + wm + mt*16 + r;
            int ncol = n0 + wn + nt*8 + q*2;
            float b0 = bias ? bias[ncol]   : 0.f;
            float b1 = bias ? bias[ncol+1] : 0.f;
            C[(long)mrow*ldc + ncol  ]     = alpha*acc[mt][nt][0] + b0;
            C[(long)mrow*ldc + ncol+1]     = alpha*acc[mt][nt][1] + b1;
            C[(long)(mrow+8)*ldc + ncol  ] = alpha*acc[mt][nt][2] + b0;
            C[(long)(mrow+8)*ldc + ncol+1] = alpha*acc[mt][nt][3] + b1;
        }
}

// ---------------------------------------------------------------------------
// Persistent LSTM recurrence — tensor-core matvec (unchanged from R8).
// ---------------------------------------------------------------------------
__global__ __launch_bounds__(256)
void lstm_persistent(const float* __restrict__ gx)
{
    extern __shared__ float sm[];
    float* Bhs = sm;                    // [16][516] presplit weight hi
    float* Bls = sm + 16*HPAD;          // [16][516] presplit weight lo
    float* hs  = sm + 32*HPAD;          // [64][516] staged h

    const int tid = threadIdx.x, bid = blockIdx.x;
    const int c0 = bid * 16;
    const int warp = tid >> 5, lane = tid & 31;
    const int mt = warp >> 1, nt = warp & 1;
    const int r = lane >> 2, q = lane & 3;
    const int row0 = mt*16 + r;

    for (int idx = tid; idx < 16*512; idx += 256) {
        int k = idx >> 4, j = idx & 15;
        float w = g_Whp[(long)k*G4 + c0 + j];
        float hi = tf32_rnd(w);
        Bhs[j*HPAD + k] = hi;
        Bls[j*HPAD + k] = tf32_rnd(w - hi);
    }

    float c_a = 0.f, c_b = 0.f;
    float* h0 = g_h[0];
    float* h1 = g_h[1];
    const int u = bid*4 + nt*2 + (q >> 1);

    __syncthreads();

    const float* arow0 = hs + row0*HPAD;
    const float* arow8 = arow0 + 8*HPAD;
    const float* brh   = Bhs + (nt*8 + r)*HPAD;
    const float* brl   = Bls + (nt*8 + r)*HPAD;

    for (int t = 0; t < S_LEN; t++) {
        const float* gbase = gx + ((long)t*BATCH)*G4 + c0 + nt*8 + 2*q;
        const float2 gA = *(const float2*)(gbase + (long)row0*G4);
        const float2 gB = *(const float2*)(gbase + (long)(row0+8)*G4);

        if (t) {
            if (tid == 0) {
                unsigned target = (unsigned)t * NB;
                while (*(volatile unsigned*)&g_cnt < target) { }
                __threadfence();
            }
            __syncthreads();
        }

        const float* hr = (t & 1) ? h1 : h0;
        #pragma unroll 8
        for (int i = 0; i < 32; i++) {
            int idx = tid + i*256;
            int rr = idx >> 7, cc = idx & 127;
            float4 v = __ldcg((const float4*)hr + idx);
            *(float4*)(hs + rr*HPAD + cc*4) = v;
        }
        __syncthreads();

        float acc[4] = {0.f, 0.f, 0.f, 0.f};
        #pragma unroll 4
        for (int k0 = 0; k0 < HID; k0 += 8) {
            float a0 = arow0[k0+q  ];
            float a1 = arow8[k0+q  ];
            float a2 = arow0[k0+q+4];
            float a3 = arow8[k0+q+4];
            float h0f = tf32_rnd(a0), h1f = tf32_rnd(a1);
            float h2f = tf32_rnd(a2), h3f = tf32_rnd(a3);
            uint32_t ah[4] = { fu(h0f), fu(h1f), fu(h2f), fu(h3f) };
            uint32_t al[4] = { fu(tf32_rnd(a0 - h0f)), fu(tf32_rnd(a1 - h1f)),
                               fu(tf32_rnd(a2 - h2f)), fu(tf32_rnd(a3 - h3f)) };
            uint32_t bh[2] = { fu(brh[k0+q]), fu(brh[k0+q+4]) };
            uint32_t bl[2] = { fu(brl[k0+q]), fu(brl[k0+q+4]) };
            MMA8(acc, ah, bh);
            MMA8(acc, ah, bl);
            MMA8(acc, al, bh);
        }

        float p0 = acc[0] + gA.x;
        float p1 = acc[1] + gA.y;
        float p2 = acc[2] + gB.x;
        float p3 = acc[3] + gB.y;

        float s0, s1, s2, s3;
        if (q & 1) {
            s0 = tanhf(p0);
            s1 = 1.f / (1.f + expf(-p1));
            s2 = tanhf(p2);
            s3 = 1.f / (1.f + expf(-p3));
        } else {
            s0 = 1.f / (1.f + expf(-p0));
            s1 = 1.f / (1.f + expf(-p1));
            s2 = 1.f / (1.f + expf(-p2));
            s3 = 1.f / (1.f + expf(-p3));
        }
        float x0 = __shfl_xor_sync(0xFFFFFFFFu, s0, 1);
        float x1 = __shfl_xor_sync(0xFFFFFFFFu, s1, 1);
        float x2 = __shfl_xor_sync(0xFFFFFFFFu, s2, 1);
        float x3 = __shfl_xor_sync(0xFFFFFFFFu, s3, 1);

        if (!(q & 1)) {
            c_a = s0 * c_a + s1 * x0;
            float hA = x1 * tanhf(c_a);
            c_b = s2 * c_b + s3 * x2;
            float hB = x3 * tanhf(c_b);

            float* hw = (t & 1) ? h0 : h1;
            hw[row0*HID + u] = hA;
            hw[(row0+8)*HID + u] = hB;
            g_lstm[((long)t*BATCH + row0)*HID + u] = hA;
            g_lstm[((long)t*BATCH + row0+8)*HID + u] = hB;
            if (t == S_LEN-1) {
                g_c[row0*HID + u] = c_a;
                g_c[(row0+8)*HID + u] = c_b;
            }
        }

        __syncthreads();
        if (tid == 0) {
            __threadfence();
            atomicAdd(&g_cnt, 1u);
        }
    }
}

// ---------------------------------------------------------------------------
// Row softmax over 512-wide rows. One block (128 threads) per row.
// ---------------------------------------------------------------------------
__global__ __launch_bounds__(128)
void softmax512(float* __restrict__ s)
{
    float* row = s + (size_t)blockIdx.x * 512;
    int tid = threadIdx.x;
    float v0 = row[tid], v1 = row[tid+128], v2 = row[tid+256], v3 = row[tid+384];
    float mx = fmaxf(fmaxf(v0, v1), fmaxf(v2, v3));
    __shared__ float sm[4];
    __shared__ float ss[4];
    #pragma unroll
    for (int off = 16; off > 0; off >>= 1)
        mx = fmaxf(mx, __shfl_xor_sync(0xFFFFFFFFu, mx, off));
    if ((tid & 31) == 0) sm[tid >> 5] = mx;
    __syncthreads();
    mx = fmaxf(fmaxf(sm[0], sm[1]), fmaxf(sm[2], sm[3]));
    v0 = expf(v0 - mx); v1 = expf(v1 - mx); v2 = expf(v2 - mx); v3 = expf(v3 - mx);
    float sum = v0 + v1 + v2 + v3;
    #pragma unroll
    for (int off = 16; off > 0; off >>= 1)
        sum += __shfl_xor_sync(0xFFFFFFFFu, sum, off);
    if ((tid & 31) == 0) ss[tid >> 5] = sum;
    __syncthreads();
    sum = ss[0] + ss[1] + ss[2] + ss[3];
    float inv = 1.f / sum;
    row[tid] = v0*inv; row[tid+128] = v1*inv; row[tid+256] = v2*inv; row[tid+384] = v3*inv;
}

__global__ void copy_hc(const float* __restrict__ h, const float* __restrict__ c,
                        float* __restrict__ out)
{
    int i = blockIdx.x * blockDim.x + threadIdx.x;
    if (i < BATCH*HID) {
        out[DEC_ELEMS + i] = h[i];
        out[DEC_ELEMS + BATCH*HID + i] = c[i];
    }
}

// ---------------------------------------------------------------------------
// Host orchestration (graph-capturable: launches only)
// ---------------------------------------------------------------------------
extern "C" void kernel_launch(void* const* d_in, const int* in_sizes, int n_in,
                              void* d_out, int out_size)
{
    const float* x  = (const float*)d_in[0];
    const float* Wf = (const float*)d_in[1];
    const float* bf = (const float*)d_in[2];
    const float* Wi = (const float*)d_in[3];
    const float* bi = (const float*)d_in[4];
    const float* Wg = (const float*)d_in[5];
    const float* bg = (const float*)d_in[6];
    const float* Wo = (const float*)d_in[7];
    const float* bo = (const float*)d_in[8];
    const float* Wq = (const float*)d_in[9];
    const float* bq = (const float*)d_in[10];
    const float* Wk = (const float*)d_in[11];
    const float* bk = (const float*)d_in[12];
    const float* Wv = (const float*)d_in[13];
    const float* bv = (const float*)d_in[14];
    float* out = (float*)d_out;

    float *Wxp, *biasp, *gx, *lstm, *hbase, *c, *PQ, *PK, *PV;
    cudaGetSymbolAddress((void**)&Wxp,   g_Wxp);
    cudaGetSymbolAddress((void**)&biasp, g_biasp);
    cudaGetSymbolAddress((void**)&gx,    g_gx);
    cudaGetSymbolAddress((void**)&lstm,  g_lstm);
    cudaGetSymbolAddress((void**)&hbase, g_h);
    cudaGetSymbolAddress((void**)&c,     g_c);
    cudaGetSymbolAddress((void**)&PQ,    g_PQ);
    cudaGetSymbolAddress((void**)&PK,    g_PK);
    cudaGetSymbolAddress((void**)&PV,    g_PV);
    float* h0 = hbase;

    const int SMEM_LSTM = (96*HPAD) * (int)sizeof(float);   // 198,144 B
    cudaFuncSetAttribute(lstm_persistent,
                         cudaFuncAttributeMaxDynamicSharedMemorySize, SMEM_LSTM);

    // 1. repack weights + zero h0 / barrier counter
    pack_weights<<<(768*HID + 255)/256, 256>>>(Wf, Wi, Wg, Wo, bf, bi, bg, bo);
    zero_state<<<(BATCH*HID + 255)/256, 256>>>();

    // 2. x-side gate preacts: gx = x @ Wxp + biasp   [32768,256]@[256,2048]
    gemm_tf32<<<dim3(G4/64, ROWS/128, 1), 256>>>(
        x, D_IN, 0, 0, Wxp, G4, 0, 0, biasp, gx, G4, 0, 0, D_IN, 1.0f, 0);

    // 3. recurrence: persistent tensor-core kernel, device grid barrier per step
    lstm_persistent<<<NB, 256, SMEM_LSTM>>>(gx);

    // 4. Q/K/V projections: [32768,512]@[512,512]+b
    gemm_tf32<<<dim3(HID/64, ROWS/128, 1), 256>>>(
        lstm, HID, 0, 0, Wq, HID, 0, 0, bq, PQ, HID, 0, 0, HID, 1.0f, 0);
    gemm_tf32<<<dim3(HID/64, ROWS/128, 1), 256>>>(
        lstm, HID, 0, 0, Wk, HID, 0, 0, bk, PK, HID, 0, 0, HID, 1.0f, 0);
    gemm_tf32<<<dim3(HID/64, ROWS/128, 1), 256>>>(
        lstm, HID, 0, 0, Wv, HID, 0, 0, bv, PV, HID, 0, 0, HID, 1.0f, 0);

    // 5. scores = (Q @ K^T)/sqrt(dk), z = b'*4 + h
    const long pbS = (long)S_LEN * HID;          // per-b' stride in PQ/PK/PV
    const long phS = DK;                         // per-h stride
    const long scB = 4L * S_LEN * S_LEN;         // scores per-b' stride
    const long scH = (long)S_LEN * S_LEN;        // scores per-h stride
    float scale = 1.0f / sqrtf((float)DK);
    gemm_tf32<<<dim3(S_LEN/64, S_LEN/128, BATCH*NH), 256>>>(
        PQ, HID, pbS, phS,
        PK, HID, pbS, phS,
        (const float*)0,
        gx /* reused as scores */, S_LEN, scB, scH, DK, scale, 1);

    // 6. softmax over last axis
    softmax512<<<BATCH*NH*S_LEN, 128>>>(gx);

    // 7. out = attn @ V, written directly in decoded layout:
    //    d_out[(s*64 + b')*512 + h*128 + d]
    gemm_tf32<<<dim3(DK/64, S_LEN/128, BATCH*NH), 256>>>(
        gx, S_LEN, scB, scH,
        PV, HID, pbS, phS,
        (const float*)0,
        out, BATCH*HID, (long)HID, (long)DK, S_LEN, 1.0f, 0);

    // 8. final hidden/cell state (after step 511 the live h buffer is h0)
    copy_hc<<<(BATCH*HID + 255)/256, 256>>>(h0, c, out);
}